// round 10
// baseline (speedup 1.0000x reference)
#include <cuda_runtime.h>
#include <cstdint>
#include <math.h>

#define BB 32
#define SS 196
#define TT 64
#define HH 1024
#define VV 32000
#define RR 4096
#define PADW 8
#define NBR 128   // recurrence grid

// k_recur smem byte offsets
#define OFF_W    128
#define OFF_X    (128 + 32768)
#define OFF_GATE (128 + 65536)
#define OFF_P2S  (OFF_GATE + 4096)
#define SMEM_RECUR (OFF_P2S + 6144)

// k_logits smem
#define SMEM_LOG (128 + 3*32768)

// ---------------- scratch ----------------
__device__ float g_M2[(size_t)BB*SS*HH];
__device__ float g_ET[(size_t)TT*RR*BB];
__device__ float g_Wf[(size_t)128*16*4096];
__device__ float g_xf[(size_t)24*4096];
__device__ float g_Af[(size_t)16*131072];
__device__ float g_Wo[(size_t)32000*1024];
__device__ float g_h [BB*HH];
__device__ float g_c [BB*HH];
__device__ float g_scores[BB*SS];
__device__ unsigned g_bar;
__device__ unsigned g_mini[BB];

// ---------------- helpers ----------------
__device__ __forceinline__ float f2tf32(float x) {
    uint32_t u; asm("cvt.rna.tf32.f32 %0, %1;" : "=r"(u) : "f"(x));
    return __uint_as_float(u);
}
__device__ __forceinline__ void mma_op(float* c, const uint32_t* a, const uint32_t* b) {
    asm volatile(
        "mma.sync.aligned.m16n8k8.row.col.f32.tf32.tf32.f32 "
        "{%0,%1,%2,%3},{%4,%5,%6,%7},{%8,%9},{%0,%1,%2,%3};"
        : "+f"(c[0]), "+f"(c[1]), "+f"(c[2]), "+f"(c[3])
        : "r"(a[0]), "r"(a[1]), "r"(a[2]), "r"(a[3]), "r"(b[0]), "r"(b[1]));
}
__device__ __forceinline__ uint32_t smem_u32(const void* p) {
    uint32_t a;
    asm("{ .reg .u64 t; cvta.to.shared.u64 t, %1; cvt.u32.u64 %0, t; }" : "=r"(a) : "l"(p));
    return a;
}
__device__ __forceinline__ size_t xf_off(int k, int n, int parity) {
    int cc = k >> 7;
    int ccp = (cc < 8) ? cc : (cc + parity * 8);
    int c8 = (k >> 3) & 15;
    int nt = n >> 3;
    int ln = ((n & 7) << 2) | (k & 3);
    int q  = (k >> 2) & 1;
    return ((size_t)(ccp * 16 + c8) * 4 + nt) * 64 + (size_t)ln * 2 + q;
}

#define MB_WAIT(mbar, par) do { uint32_t _d; \
    do { asm volatile("{\n\t.reg .pred p;\n\t" \
        "mbarrier.try_wait.parity.acquire.cta.shared::cta.b64 p, [%1], %2;\n\t" \
        "selp.b32 %0, 1, 0, p;\n\t}" \
        : "=r"(_d) : "r"(mbar), "r"((uint32_t)(par)) : "memory"); } while (!_d); } while (0)

// ---------------- tf32 GEMM (prologue M2 / E only) ----------------
__global__ __launch_bounds__(256, 2) void mma_gemm(
    const float* __restrict__ A, const float* __restrict__ Bsrc,
    float* __restrict__ C, int M, int N, int K, int ldb,
    const int* __restrict__ gatherIdx, const float* __restrict__ gatherTab,
    int mode)
{
    __shared__ float As[16][128 + PADW];
    __shared__ float Bs[16][128 + PADW];
    int tid = threadIdx.x;
    int n0 = blockIdx.x * 128, m0 = blockIdx.y * 128;
    int warp = tid >> 5, lane = tid & 31;
    int wm = warp >> 1, wn = warp & 1;
    int grp = lane >> 2, tg = lane & 3;

    float acc[2][8][4] = {};

    const float* arow[2];
    int ac4[2];
    #pragma unroll
    for (int it = 0; it < 2; it++) {
        int idx = tid + it * 256;
        int r = idx >> 2; ac4[it] = (idx & 3) * 4;
        arow[it] = gatherIdx ? (gatherTab + (size_t)gatherIdx[m0 + r] * K)
                             : (A + (size_t)(m0 + r) * K);
    }

    for (int k0 = 0; k0 < K; k0 += 16) {
        #pragma unroll
        for (int it = 0; it < 2; it++) {
            int idx = tid + it * 256;
            int r = idx >> 2;
            float4 v = *(const float4*)(arow[it] + k0 + ac4[it]);
            As[ac4[it]+0][r] = f2tf32(v.x); As[ac4[it]+1][r] = f2tf32(v.y);
            As[ac4[it]+2][r] = f2tf32(v.z); As[ac4[it]+3][r] = f2tf32(v.w);
        }
        if (mode == 2) {
            #pragma unroll
            for (int it = 0; it < 2; it++) {
                int idx = tid + it * 256;
                int r = idx >> 5, c4 = (idx & 31) * 4;
                float4 v = *(const float4*)(Bsrc + (size_t)(k0 + r) * ldb + n0 + c4);
                Bs[r][c4+0] = f2tf32(v.x); Bs[r][c4+1] = f2tf32(v.y);
                Bs[r][c4+2] = f2tf32(v.z); Bs[r][c4+3] = f2tf32(v.w);
            }
        } else {
            #pragma unroll
            for (int it = 0; it < 2; it++) {
                int idx = tid + it * 256;
                int r = idx >> 2, c4 = (idx & 3) * 4;
                float4 v = *(const float4*)(Bsrc + (size_t)(n0 + r) * ldb + k0 + c4);
                Bs[c4+0][r] = f2tf32(v.x); Bs[c4+1][r] = f2tf32(v.y);
                Bs[c4+2][r] = f2tf32(v.z); Bs[c4+3][r] = f2tf32(v.w);
            }
        }
        __syncthreads();

        #pragma unroll
        for (int ks = 0; ks < 2; ks++) {
            int kb = ks * 8;
            uint32_t af[2][4], bf[8][2];
            #pragma unroll
            for (int mt = 0; mt < 2; mt++) {
                int r = wm * 32 + mt * 16 + grp;
                af[mt][0] = __float_as_uint(As[kb+tg  ][r  ]);
                af[mt][1] = __float_as_uint(As[kb+tg  ][r+8]);
                af[mt][2] = __float_as_uint(As[kb+tg+4][r  ]);
                af[mt][3] = __float_as_uint(As[kb+tg+4][r+8]);
            }
            #pragma unroll
            for (int nt = 0; nt < 8; nt++) {
                int cix = wn * 64 + nt * 8 + grp;
                bf[nt][0] = __float_as_uint(Bs[kb+tg  ][cix]);
                bf[nt][1] = __float_as_uint(Bs[kb+tg+4][cix]);
            }
            #pragma unroll
            for (int mt = 0; mt < 2; mt++)
                #pragma unroll
                for (int nt = 0; nt < 8; nt++)
                    mma_op(acc[mt][nt], af[mt], bf[nt]);
        }
        __syncthreads();
    }

    #pragma unroll
    for (int mt = 0; mt < 2; mt++) {
        int mg = m0 + wm * 32 + mt * 16 + grp;
        #pragma unroll
        for (int nt = 0; nt < 8; nt++) {
            int ng = n0 + wn * 64 + nt * 8 + tg * 2;
            float* a4 = acc[mt][nt];
            if (mode == 3) {
                int b1i = mg >> 6,     t1 = mg & 63;
                int b2i = (mg+8) >> 6, t2 = (mg+8) & 63;
                size_t p1 = ((size_t)t1 * RR + ng) * 32 + b1i;
                size_t p2 = ((size_t)t2 * RR + ng) * 32 + b2i;
                C[p1] = a4[0]; C[p1 + 32] = a4[1];
                C[p2] = a4[2]; C[p2 + 32] = a4[3];
            } else {
                *(float2*)(C + (size_t)mg * N + ng)       = make_float2(a4[0], a4[1]);
                *(float2*)(C + (size_t)(mg + 8) * N + ng) = make_float2(a4[2], a4[3]);
            }
        }
    }
}

// ---------------- gate weight fragment pack ----------------
__global__ __launch_bounds__(256) void k_packWF(
    const float* __restrict__ W_ih, const float* __restrict__ W_hh)
{
    int idx = blockIdx.x * 256 + threadIdx.x;
    int lane = idx & 31;
    int mt   = (idx >> 5) & 1;
    int c8   = (idx >> 6) & 15;
    int cc   = (idx >> 10) & 15;
    int blk  = idx >> 14;
    float4 v;
    float* o = (float*)&v;
    #pragma unroll
    for (int q = 0; q < 4; q++) {
        int m = mt * 16 + (lane >> 2) + 8 * (q & 1);
        int g = m >> 3, jo = m & 7;
        int r = g * 1024 + blk * 8 + jo;
        int k = (cc * 16 + c8) * 8 + (lane & 3) + 4 * (q >> 1);
        float wv = (k < 1024) ? W_ih[(size_t)r * 2048 + 1024 + k]
                              : W_hh[(size_t)r * 1024 + (k - 1024)];
        o[q] = f2tf32(wv);
    }
    ((float4*)g_Wf)[idx] = v;
}

// ---------------- W_out fragment pack ----------------
__global__ __launch_bounds__(256) void k_packWo(const float* __restrict__ W_out)
{
    size_t idx = (size_t)blockIdx.x * 256 + threadIdx.x;
    int lane = (int)(idx & 31);
    int nt   = (int)((idx >> 5) & 15);
    int c8   = (int)((idx >> 9) & 127);
    int nblk = (int)(idx >> 16);
    int n = nblk * 128 + nt * 8 + (lane >> 2);
    int k = c8 * 8 + (lane & 3);
    float2 v;
    v.x = f2tf32(W_out[(size_t)n * HH + k]);
    v.y = f2tf32(W_out[(size_t)n * HH + k + 4]);
    ((float2*)g_Wo)[idx] = v;
}

// ---------------- no-CCTL global barrier ----------------
__device__ __forceinline__ void gridbar(unsigned target) {
    __syncthreads();
    if (threadIdx.x == 0) {
        unsigned one = 1u, x;
        asm volatile("red.release.gpu.global.add.u32 [%0], %1;"
                     :: "l"(&g_bar), "r"(one) : "memory");
        do {
            asm volatile("ld.acquire.gpu.global.u32 %0, [%1];"
                         : "=r"(x) : "l"(&g_bar));
        } while (x < target);
    }
    __syncthreads();
}

// ---------------- persistent recurrence: 2 barriers/step ----------------
__global__ __launch_bounds__(1024, 1) void k_recur(
    const float* __restrict__ memory,
    const float* __restrict__ b_ih, const float* __restrict__ b_hh)
{
    extern __shared__ char smem[];
    float* gate_s = (float*)(smem + OFF_GATE);
    float* p2s    = (float*)(smem + OFF_P2S);      // swp[256] | part[768]
    const uint32_t sbase = smem_u32(smem);
    const uint32_t mbA[2] = { sbase, sbase + 8 };

    const int tid = threadIdx.x, bid = blockIdx.x;
    const int lane = tid & 31;
    const int b_att = bid >> 2, q_att = bid & 3;

    if (tid == 0) {
        asm volatile("mbarrier.init.shared.b64 [%0], %1;" :: "r"(mbA[0]), "r"(1u) : "memory");
        asm volatile("mbarrier.init.shared.b64 [%0], %1;" :: "r"(mbA[1]), "r"(1u) : "memory");
    }
    __syncthreads();

    unsigned tgt = NBR;

    for (int t = 0; t < TT; t++) {
        const int par = t & 1;
        float acc[4] = {0.f, 0.f, 0.f, 0.f};    // carried across the mid-step barrier
        const int w8 = tid >> 5;
        const int mt = w8 & 1, nt = w8 >> 1;     // valid for tid<256
        const int grp = lane >> 2, tg = lane & 3;

        // issue chunk cc (0..15): weights [bid][cc]; x chunk ccp
        auto issue = [&](int cc, int idx) {
            uint32_t mb = mbA[idx & 1];
            uint32_t wd = sbase + OFF_W + (idx & 1) * 16384;
            uint32_t xd = sbase + OFF_X + (idx & 1) * 16384;
            const float* ws = g_Wf + ((size_t)bid * 16 + cc) * 4096;
            int ccp = (cc < 8) ? cc : (cc + par * 8);
            const float* xs = g_xf + (size_t)ccp * 4096;
            asm volatile("mbarrier.arrive.expect_tx.shared.b64 _, [%0], %1;"
                         :: "r"(mb), "r"(32768u) : "memory");
            asm volatile("cp.async.bulk.shared::cta.global.mbarrier::complete_tx::bytes "
                         "[%0], [%1], %2, [%3];"
                         :: "r"(wd), "l"(ws), "r"(16384u), "r"(mb) : "memory");
            asm volatile("cp.async.bulk.shared::cta.global.mbarrier::complete_tx::bytes "
                         "[%0], [%1], %2, [%3];"
                         :: "r"(xd), "l"(xs), "r"(16384u), "r"(mb) : "memory");
        };
        // consume pipeline of 8 chunks starting at ccbase
        auto run8 = [&](int ccbase) {
            if (tid == 0) { issue(ccbase, 0); issue(ccbase + 1, 1); }
            #pragma unroll
            for (int i = 0; i < 8; i++) {
                MB_WAIT(mbA[i & 1], (i >> 1) & 1);
                const float4* wb = (const float4*)(smem + OFF_W + (i & 1) * 16384);
                const float2* xb = (const float2*)(smem + OFF_X + (i & 1) * 16384);
                #pragma unroll
                for (int c8 = 0; c8 < 16; c8++) {
                    float4 a4 = wb[(c8 * 2 + mt) * 32 + lane];
                    float2 b2 = xb[(c8 * 4 + nt) * 32 + lane];
                    mma_op(acc, (const uint32_t*)&a4, (const uint32_t*)&b2);
                }
                asm volatile("bar.sync 7, 256;" ::: "memory");
                if (tid == 0 && i < 6) issue(ccbase + i + 2, i + 2);
            }
        };

        // ================= Phase A =================
        if (tid < 256) {
            run8(8);                               // W_hh @ h (h-half)
        } else {
            int tid2 = tid - 256;                  // 0..767
            int ws = tid2 >> 5;                    // 0..23
            // ---- scores for batch b_att, rows q_att*49 .. +48 ----
            for (int si = ws; si < 49; si += 24) {
                int p = b_att * SS + q_att * 49 + si;
                const float4* m4 = (const float4*)(g_M2 + (size_t)p * HH);
                const float4* h4 = (const float4*)(g_h + b_att * HH);
                float a = 0.f;
                #pragma unroll
                for (int i = 0; i < 8; i++) {
                    float4 mv = m4[i * 32 + lane];
                    float4 hv = __ldcg(&h4[i * 32 + lane]);
                    a += mv.x*hv.x + mv.y*hv.y + mv.z*hv.z + mv.w*hv.w;
                }
                #pragma unroll
                for (int o = 16; o; o >>= 1) a += __shfl_xor_sync(0xffffffffu, a, o);
                if (!lane) g_scores[p] = a;
            }
            asm volatile("bar.sync 1, 768;" ::: "memory");
            // ---- 4-block mini-barrier for batch b_att ----
            if (tid2 == 0) {
                unsigned one = 1u, x, want = 4u * (unsigned)(t + 1);
                asm volatile("red.release.gpu.global.add.u32 [%0], %1;"
                             :: "l"(&g_mini[b_att]), "r"(one) : "memory");
                do {
                    asm volatile("ld.acquire.gpu.global.u32 %0, [%1];"
                                 : "=r"(x) : "l"(&g_mini[b_att]));
                } while (x < want);
            }
            asm volatile("bar.sync 1, 768;" ::: "memory");
            // ---- softmax over 196 (warp ws==23) ----
            float* swp  = p2s;
            float* part = p2s + 256;
            if (ws == 23) {
                float vals[7]; float mx = -1e30f;
                #pragma unroll
                for (int i = 0; i < 7; i++) {
                    int s = lane + 32 * i;
                    float v = (s < SS) ? __ldcg(&g_scores[b_att * SS + s]) : -1e30f;
                    vals[i] = v; mx = fmaxf(mx, v);
                }
                #pragma unroll
                for (int o = 16; o; o >>= 1) mx = fmaxf(mx, __shfl_xor_sync(0xffffffffu, mx, o));
                float se = 0.f;
                #pragma unroll
                for (int i = 0; i < 7; i++) {
                    int s = lane + 32 * i;
                    float e = (s < SS) ? expf(vals[i] - mx) : 0.f;
                    vals[i] = e; se += e;
                }
                #pragma unroll
                for (int o = 16; o; o >>= 1) se += __shfl_xor_sync(0xffffffffu, se, o);
                float inv = 1.f / se;
                #pragma unroll
                for (int i = 0; i < 7; i++) {
                    int s = lane + 32 * i;
                    if (s < SS) swp[s] = vals[i] * inv;
                }
            }
            asm volatile("bar.sync 1, 768;" ::: "memory");
            // ---- ctx: j slice q_att*256..+255, s split 3 ways ----
            int grp3 = ws >> 3;                    // 0..2
            int jj = tid2 & 255;
            int j = q_att * 256 + jj;
            int s0 = grp3 * 66;
            int s1 = (grp3 == 2) ? SS : (s0 + 66);
            const float* mp = memory + ((size_t)b_att * SS) * HH + j;
            float a = 0.f;
            #pragma unroll 6
            for (int s = s0; s < s1; s++)
                a += swp[s] * __ldg(&mp[(size_t)s * HH]);
            part[grp3 * 256 + jj] = a;
            asm volatile("bar.sync 1, 768;" ::: "memory");
            if (grp3 == 0) {
                float cv = part[jj] + part[256 + jj] + part[512 + jj];
                g_xf[xf_off(j, b_att, 0)] = f2tf32(cv);
            }
        }
        gridbar(tgt); tgt += NBR;

        // ================= Phase B: ctx-half gates + cell =================
        if (tid < 256) {
            run8(0);                               // W_ih_ctx @ ctx (acc continues)
            *(float2*)&gate_s[(mt*16 + grp    ) * 32 + nt*8 + tg*2] = make_float2(acc[0], acc[1]);
            *(float2*)&gate_s[(mt*16 + grp + 8) * 32 + nt*8 + tg*2] = make_float2(acc[2], acc[3]);
            asm volatile("bar.sync 7, 256;" ::: "memory");
            {
                int b = tid & 31, jo = tid >> 5;
                int j = bid * 8 + jo;
                float pre[4];
                #pragma unroll
                for (int g = 0; g < 4; g++) {
                    pre[g] = gate_s[(g*8 + jo) * 32 + b]
                           + __ldg(&g_ET[((size_t)t * RR + g*1024 + j) * 32 + b])
                           + __ldg(&b_ih[g*1024 + j]) + __ldg(&b_hh[g*1024 + j]);
                }
                float ig = 1.f / (1.f + expf(-pre[0]));
                float fg = 1.f / (1.f + expf(-pre[1]));
                float gg = tanhf(pre[2]);
                float og = 1.f / (1.f + expf(-pre[3]));
                int idx = b * HH + j;
                float cn = fg * g_c[idx] + ig * gg;
                float hn = og * tanhf(cn);
                g_c[idx] = cn;
                g_h[idx] = hn;
                g_xf[xf_off(1024 + j, b, (t + 1) & 1)] = f2tf32(hn);
                int m = t * 32 + b;
                int mblk = m >> 7, mtile = (m >> 4) & 7;
                int q = ((m >> 3) & 1) + 2 * ((j >> 2) & 1);
                int lnA = ((m & 7) << 2) | (j & 3);
                g_Af[((((size_t)mblk * 128 + (j >> 3)) * 8 + mtile) * 32 + lnA) * 4 + q]
                    = f2tf32(hn);
            }
        }
        gridbar(tgt); tgt += NBR;
    }
}

// ---------------- pipelined logits GEMM (unchanged from R9) ----------------
__global__ __launch_bounds__(256, 2) void k_logits(
    const float* __restrict__ bias, float* __restrict__ out)
{
    extern __shared__ char smem[];
    const uint32_t sbase = smem_u32(smem);
    const int tid = threadIdx.x;
    const int mblk = blockIdx.x, nblk = blockIdx.y;
    const int warp = tid >> 5, lane = tid & 31;
    const int wm = warp >> 1, wn = warp & 1;
    const int grp = lane >> 2, tg = lane & 3;

    if (tid == 0) {
        #pragma unroll
        for (int i = 0; i < 3; i++)
            asm volatile("mbarrier.init.shared.b64 [%0], %1;"
                         :: "r"(sbase + i * 8), "r"(1u) : "memory");
    }
    __syncthreads();

    float acc[2][8][4] = {};

    auto issue = [&](int s) {
        int buf = s % 3;
        uint32_t mb = sbase + buf * 8;
        uint32_t ad = sbase + 128 + buf * 32768;
        uint32_t bd = ad + 16384;
        const float* as = g_Af + ((size_t)mblk * 128 + s * 4) * 1024;
        const float* bs = g_Wo + ((size_t)nblk * 128 + s * 4) * 1024;
        asm volatile("mbarrier.arrive.expect_tx.shared.b64 _, [%0], %1;"
                     :: "r"(mb), "r"(32768u) : "memory");
        asm volatile("cp.async.bulk.shared::cta.global.mbarrier::complete_tx::bytes "
                     "[%0], [%1], %2, [%3];"
                     :: "r"(ad), "l"(as), "r"(16384u), "r"(mb) : "memory");
        asm volatile("cp.async.bulk.shared::cta.global.mbarrier::complete_tx::bytes "
                     "[%0], [%1], %2, [%3];"
                     :: "r"(bd), "l"(bs), "r"(16384u), "r"(mb) : "memory");
    };

    if (tid == 0) { issue(0); issue(1); }

    for (int s = 0; s < 32; s++) {
        int buf = s % 3;
        MB_WAIT(sbase + buf * 8, (s / 3) & 1);
        const float4* Ab = (const float4*)(smem + 128 + buf * 32768);
        const float2* Bb = (const float2*)(smem + 128 + buf * 32768 + 16384);
        #pragma unroll
        for (int c8 = 0; c8 < 4; c8++) {
            float4 a0 = Ab[(c8 * 8 + wm * 2 + 0) * 32 + lane];
            float4 a1 = Ab[(c8 * 8 + wm * 2 + 1) * 32 + lane];
            #pragma unroll
            for (int nt = 0; nt < 8; nt++) {
                float2 b2 = Bb[(c8 * 16 + wn * 8 + nt) * 32 + lane];
                mma_op(acc[0][nt], (const uint32_t*)&a0, (const uint32_t*)&b2);
                mma_op(acc[1][nt], (const uint32_t*)&a1, (const uint32_t*)&b2);
            }
        }
        __syncthreads();
        if (tid == 0 && s + 2 < 32) issue(s + 2);
    }

    #pragma unroll
    for (int mt = 0; mt < 2; mt++) {
        int m0 = mblk * 128 + (wm * 2 + mt) * 16 + grp;
        #pragma unroll
        for (int nt = 0; nt < 8; nt++) {
            int ng = nblk * 128 + wn * 64 + nt * 8 + tg * 2;
            float b0 = __ldg(bias + ng), b1 = __ldg(bias + ng + 1);
            int m2 = m0 + 8;
            size_t r1 = ((size_t)(m0 & 31) * TT + (m0 >> 5)) * VV;
            size_t r2 = ((size_t)(m2 & 31) * TT + (m2 >> 5)) * VV;
            *(float2*)(out + r1 + ng) = make_float2(acc[mt][nt][0] + b0, acc[mt][nt][1] + b1);
            *(float2*)(out + r2 + ng) = make_float2(acc[mt][nt][2] + b0, acc[mt][nt][3] + b1);
        }
    }
}

// ---------------- small kernels ----------------
__global__ void k_zero() {
    int i = blockIdx.x * 1024 + threadIdx.x;
    g_h[i] = 0.f; g_c[i] = 0.f;
    g_xf[i] = 0.f; g_xf[i + 32768] = 0.f; g_xf[i + 65536] = 0.f;
    if (i == 0) g_bar = 0u;
    if (i < BB) g_mini[i] = 0u;
}

__global__ void k_copy_hc(float* __restrict__ out) {
    int i = blockIdx.x * 512 + threadIdx.x;
    const size_t OFF = (size_t)BB * TT * VV;
    out[OFF + i] = g_h[i];
    out[OFF + (size_t)BB*HH + i] = g_c[i];
}

// ---------------- launch ----------------
extern "C" void kernel_launch(void* const* d_in, const int* in_sizes, int n_in,
                              void* d_out, int out_size)
{
    const float* memory  = (const float*)d_in[0];
    const int*   captions= (const int*  )d_in[1];
    const float* emb     = (const float*)d_in[2];
    const float* attn_W  = (const float*)d_in[3];
    const float* W_ih    = (const float*)d_in[4];
    const float* W_hh    = (const float*)d_in[5];
    const float* b_ih    = (const float*)d_in[6];
    const float* b_hh    = (const float*)d_in[7];
    const float* W_out   = (const float*)d_in[8];
    const float* b_out   = (const float*)d_in[9];
    float* out = (float*)d_out;

    static float *pM2 = nullptr, *pET = nullptr;
    if (!pM2) {
        cudaGetSymbolAddress((void**)&pM2, g_M2);
        cudaGetSymbolAddress((void**)&pET, g_ET);
        cudaFuncSetAttribute(k_recur,  cudaFuncAttributeMaxDynamicSharedMemorySize, SMEM_RECUR);
        cudaFuncSetAttribute(k_logits, cudaFuncAttributeMaxDynamicSharedMemorySize, SMEM_LOG);
    }

    k_zero<<<32, 1024>>>();

    // M2 = memory @ attn_W
    mma_gemm<<<dim3(HH/128, (BB*SS)/128), 256>>>(
        memory, attn_W, pM2, BB*SS, HH, HH, HH,
        nullptr, nullptr, 2);

    // E^T
    mma_gemm<<<dim3(RR/128, (BB*TT)/128), 256>>>(
        nullptr, W_ih, pET, BB*TT, RR, HH, 2048,
        captions, emb, 3);

    // fragment packs
    k_packWF<<<8192, 256>>>(W_ih, W_hh);
    k_packWo<<<64000, 256>>>(W_out);

    // recurrence (2 grid barriers / step)
    k_recur<<<NBR, 1024, SMEM_RECUR>>>(memory, b_ih, b_hh);

    // logits
    k_logits<<<dim3(16, 250), 256, SMEM_LOG>>>(b_out, out);

    k_copy_hc<<<64, 512>>>(out);
}

// round 11
// speedup vs baseline: 1.4501x; 1.4501x over previous
#include <cuda_runtime.h>
#include <cstdint>
#include <math.h>

#define BB 32
#define SS 196
#define TT 64
#define HH 1024
#define VV 32000
#define RR 4096
#define PADW 8
#define NB 148

// k_recur smem byte offsets
#define OFF_W    128
#define OFF_X    (128 + 32768)
#define OFF_GATE (128 + 65536)
#define OFF_P2S  (OFF_GATE + 4096)
#define SMEM_RECUR (OFF_P2S + 6144)

// k_logits smem
#define SMEM_LOG (128 + 3*32768)

// ---------------- scratch ----------------
__device__ float g_M2[(size_t)BB*SS*HH];
__device__ float g_ET[(size_t)TT*RR*BB];
__device__ float g_Wf[(size_t)128*16*4096];
__device__ float g_xf[(size_t)24*4096];
__device__ float g_Af[(size_t)16*131072];
__device__ float g_Wo[(size_t)32000*1024];
__device__ float g_h [BB*HH];
__device__ float g_c [BB*HH];
__device__ float g_scores[BB*SS];
__device__ unsigned g_bar;
__device__ unsigned g_p2done;

// ---------------- helpers ----------------
__device__ __forceinline__ float f2tf32(float x) {
    uint32_t u; asm("cvt.rna.tf32.f32 %0, %1;" : "=r"(u) : "f"(x));
    return __uint_as_float(u);
}
__device__ __forceinline__ void mma_op(float* c, const uint32_t* a, const uint32_t* b) {
    asm volatile(
        "mma.sync.aligned.m16n8k8.row.col.f32.tf32.tf32.f32 "
        "{%0,%1,%2,%3},{%4,%5,%6,%7},{%8,%9},{%0,%1,%2,%3};"
        : "+f"(c[0]), "+f"(c[1]), "+f"(c[2]), "+f"(c[3])
        : "r"(a[0]), "r"(a[1]), "r"(a[2]), "r"(a[3]), "r"(b[0]), "r"(b[1]));
}
__device__ __forceinline__ uint32_t smem_u32(const void* p) {
    uint32_t a;
    asm("{ .reg .u64 t; cvta.to.shared.u64 t, %1; cvt.u32.u64 %0, t; }" : "=r"(a) : "l"(p));
    return a;
}
__device__ __forceinline__ size_t xf_off(int k, int n, int parity) {
    int cc = k >> 7;
    int ccp = (cc < 8) ? cc : (cc + parity * 8);
    int c8 = (k >> 3) & 15;
    int nt = n >> 3;
    int ln = ((n & 7) << 2) | (k & 3);
    int q  = (k >> 2) & 1;
    return ((size_t)(ccp * 16 + c8) * 4 + nt) * 64 + (size_t)ln * 2 + q;
}

#define MB_WAIT(mbar, par) do { uint32_t _d; \
    do { asm volatile("{\n\t.reg .pred p;\n\t" \
        "mbarrier.try_wait.parity.acquire.cta.shared::cta.b64 p, [%1], %2;\n\t" \
        "selp.b32 %0, 1, 0, p;\n\t}" \
        : "=r"(_d) : "r"(mbar), "r"((uint32_t)(par)) : "memory"); } while (!_d); } while (0)

// ---------------- tf32 GEMM (prologue M2 / E only) ----------------
__global__ __launch_bounds__(256, 2) void mma_gemm(
    const float* __restrict__ A, const float* __restrict__ Bsrc,
    float* __restrict__ C, int M, int N, int K, int ldb,
    const int* __restrict__ gatherIdx, const float* __restrict__ gatherTab,
    int mode)
{
    __shared__ float As[16][128 + PADW];
    __shared__ float Bs[16][128 + PADW];
    int tid = threadIdx.x;
    int n0 = blockIdx.x * 128, m0 = blockIdx.y * 128;
    int warp = tid >> 5, lane = tid & 31;
    int wm = warp >> 1, wn = warp & 1;
    int grp = lane >> 2, tg = lane & 3;

    float acc[2][8][4] = {};

    const float* arow[2];
    int ac4[2];
    #pragma unroll
    for (int it = 0; it < 2; it++) {
        int idx = tid + it * 256;
        int r = idx >> 2; ac4[it] = (idx & 3) * 4;
        arow[it] = gatherIdx ? (gatherTab + (size_t)gatherIdx[m0 + r] * K)
                             : (A + (size_t)(m0 + r) * K);
    }

    for (int k0 = 0; k0 < K; k0 += 16) {
        #pragma unroll
        for (int it = 0; it < 2; it++) {
            int idx = tid + it * 256;
            int r = idx >> 2;
            float4 v = *(const float4*)(arow[it] + k0 + ac4[it]);
            As[ac4[it]+0][r] = f2tf32(v.x); As[ac4[it]+1][r] = f2tf32(v.y);
            As[ac4[it]+2][r] = f2tf32(v.z); As[ac4[it]+3][r] = f2tf32(v.w);
        }
        if (mode == 2) {
            #pragma unroll
            for (int it = 0; it < 2; it++) {
                int idx = tid + it * 256;
                int r = idx >> 5, c4 = (idx & 31) * 4;
                float4 v = *(const float4*)(Bsrc + (size_t)(k0 + r) * ldb + n0 + c4);
                Bs[r][c4+0] = f2tf32(v.x); Bs[r][c4+1] = f2tf32(v.y);
                Bs[r][c4+2] = f2tf32(v.z); Bs[r][c4+3] = f2tf32(v.w);
            }
        } else {
            #pragma unroll
            for (int it = 0; it < 2; it++) {
                int idx = tid + it * 256;
                int r = idx >> 2, c4 = (idx & 3) * 4;
                float4 v = *(const float4*)(Bsrc + (size_t)(n0 + r) * ldb + k0 + c4);
                Bs[c4+0][r] = f2tf32(v.x); Bs[c4+1][r] = f2tf32(v.y);
                Bs[c4+2][r] = f2tf32(v.z); Bs[c4+3][r] = f2tf32(v.w);
            }
        }
        __syncthreads();

        #pragma unroll
        for (int ks = 0; ks < 2; ks++) {
            int kb = ks * 8;
            uint32_t af[2][4], bf[8][2];
            #pragma unroll
            for (int mt = 0; mt < 2; mt++) {
                int r = wm * 32 + mt * 16 + grp;
                af[mt][0] = __float_as_uint(As[kb+tg  ][r  ]);
                af[mt][1] = __float_as_uint(As[kb+tg  ][r+8]);
                af[mt][2] = __float_as_uint(As[kb+tg+4][r  ]);
                af[mt][3] = __float_as_uint(As[kb+tg+4][r+8]);
            }
            #pragma unroll
            for (int nt = 0; nt < 8; nt++) {
                int cix = wn * 64 + nt * 8 + grp;
                bf[nt][0] = __float_as_uint(Bs[kb+tg  ][cix]);
                bf[nt][1] = __float_as_uint(Bs[kb+tg+4][cix]);
            }
            #pragma unroll
            for (int mt = 0; mt < 2; mt++)
                #pragma unroll
                for (int nt = 0; nt < 8; nt++)
                    mma_op(acc[mt][nt], af[mt], bf[nt]);
        }
        __syncthreads();
    }

    #pragma unroll
    for (int mt = 0; mt < 2; mt++) {
        int mg = m0 + wm * 32 + mt * 16 + grp;
        #pragma unroll
        for (int nt = 0; nt < 8; nt++) {
            int ng = n0 + wn * 64 + nt * 8 + tg * 2;
            float* a4 = acc[mt][nt];
            if (mode == 3) {
                int b1i = mg >> 6,     t1 = mg & 63;
                int b2i = (mg+8) >> 6, t2 = (mg+8) & 63;
                size_t p1 = ((size_t)t1 * RR + ng) * 32 + b1i;
                size_t p2 = ((size_t)t2 * RR + ng) * 32 + b2i;
                C[p1] = a4[0]; C[p1 + 32] = a4[1];
                C[p2] = a4[2]; C[p2 + 32] = a4[3];
            } else {
                *(float2*)(C + (size_t)mg * N + ng)       = make_float2(a4[0], a4[1]);
                *(float2*)(C + (size_t)(mg + 8) * N + ng) = make_float2(a4[2], a4[3]);
            }
        }
    }
}

// ---------------- gate weight fragment pack ----------------
__global__ __launch_bounds__(256) void k_packWF(
    const float* __restrict__ W_ih, const float* __restrict__ W_hh)
{
    int idx = blockIdx.x * 256 + threadIdx.x;
    int lane = idx & 31;
    int mt   = (idx >> 5) & 1;
    int c8   = (idx >> 6) & 15;
    int cc   = (idx >> 10) & 15;
    int blk  = idx >> 14;
    float4 v;
    float* o = (float*)&v;
    #pragma unroll
    for (int q = 0; q < 4; q++) {
        int m = mt * 16 + (lane >> 2) + 8 * (q & 1);
        int g = m >> 3, jo = m & 7;
        int r = g * 1024 + blk * 8 + jo;
        int k = (cc * 16 + c8) * 8 + (lane & 3) + 4 * (q >> 1);
        float wv = (k < 1024) ? W_ih[(size_t)r * 2048 + 1024 + k]
                              : W_hh[(size_t)r * 1024 + (k - 1024)];
        o[q] = f2tf32(wv);
    }
    ((float4*)g_Wf)[idx] = v;
}

// ---------------- W_out fragment pack ----------------
__global__ __launch_bounds__(256) void k_packWo(const float* __restrict__ W_out)
{
    size_t idx = (size_t)blockIdx.x * 256 + threadIdx.x;
    int lane = (int)(idx & 31);
    int nt   = (int)((idx >> 5) & 15);
    int c8   = (int)((idx >> 9) & 127);
    int nblk = (int)(idx >> 16);
    int n = nblk * 128 + nt * 8 + (lane >> 2);
    int k = c8 * 8 + (lane & 3);
    float2 v;
    v.x = f2tf32(W_out[(size_t)n * HH + k]);
    v.y = f2tf32(W_out[(size_t)n * HH + k + 4]);
    ((float2*)g_Wo)[idx] = v;
}

// ---------------- no-CCTL global barrier ----------------
__device__ __forceinline__ void gridbar(unsigned target) {
    __syncthreads();
    if (threadIdx.x == 0) {
        unsigned one = 1u, x;
        asm volatile("red.release.gpu.global.add.u32 [%0], %1;"
                     :: "l"(&g_bar), "r"(one) : "memory");
        do {
            asm volatile("ld.acquire.gpu.global.u32 %0, [%1];"
                         : "=r"(x) : "l"(&g_bar));
        } while (x < target);
    }
    __syncthreads();
}

// ---------------- persistent recurrence (R9 + h-first pipeline, 2 barriers/step) ----------------
__global__ __launch_bounds__(1024, 1) void k_recur(
    const float* __restrict__ memory,
    const float* __restrict__ b_ih, const float* __restrict__ b_hh)
{
    extern __shared__ char smem[];
    float* gate_s = (float*)(smem + OFF_GATE);
    float* p2s    = (float*)(smem + OFF_P2S);
    const uint32_t sbase = smem_u32(smem);
    const uint32_t mb0 = sbase, mb1 = sbase + 8;

    const int tid = threadIdx.x, bid = blockIdx.x;
    const int w = tid >> 5, lane = tid & 31;
    const bool gateblk = (bid < 128);

    if (tid == 0) {
        asm volatile("mbarrier.init.shared.b64 [%0], %1;" :: "r"(mb0), "r"(1u) : "memory");
        asm volatile("mbarrier.init.shared.b64 [%0], %1;" :: "r"(mb1), "r"(1u) : "memory");
    }
    __syncthreads();

    unsigned tgt = NB;

    for (int t = 0; t < TT; t++) {
        const int par = t & 1;

        // issue chunk cc into pipeline slot (slot parity picks buffer/mbarrier)
        auto issue = [&](int cc, int slot) {
            uint32_t mb = (slot & 1) ? mb1 : mb0;
            uint32_t wd = sbase + OFF_W + (slot & 1) * 16384;
            uint32_t xd = sbase + OFF_X + (slot & 1) * 16384;
            const float* ws = g_Wf + ((size_t)bid * 16 + cc) * 4096;
            int ccp = (cc < 8) ? cc : (cc + par * 8);
            const float* xs = g_xf + (size_t)ccp * 4096;
            asm volatile("mbarrier.arrive.expect_tx.shared.b64 _, [%0], %1;"
                         :: "r"(mb), "r"(32768u) : "memory");
            asm volatile("cp.async.bulk.shared::cta.global.mbarrier::complete_tx::bytes "
                         "[%0], [%1], %2, [%3];"
                         :: "r"(wd), "l"(ws), "r"(16384u), "r"(mb) : "memory");
            asm volatile("cp.async.bulk.shared::cta.global.mbarrier::complete_tx::bytes "
                         "[%0], [%1], %2, [%3];"
                         :: "r"(xd), "l"(xs), "r"(16384u), "r"(mb) : "memory");
        };

        // ---- early issue: h-half chunks 8,9 fly during P1/P2 ----
        if (gateblk && tid == 0) { issue(8, 0); issue(9, 1); }

        // ======== P1: scores (all 148 blocks) ========
        for (int p = bid * 32 + w; p < BB * SS; p += NB * 32) {
            int b = p / SS;
            const float4* m4 = (const float4*)(g_M2 + (size_t)p * HH);
            const float4* h4 = (const float4*)(g_h + b * HH);
            float a = 0.f;
            #pragma unroll
            for (int i = 0; i < 8; i++) {
                float4 mv = m4[i * 32 + lane];
                float4 hv = __ldcg(&h4[i * 32 + lane]);
                a += mv.x*hv.x + mv.y*hv.y + mv.z*hv.z + mv.w*hv.w;
            }
            #pragma unroll
            for (int o = 16; o; o >>= 1) a += __shfl_xor_sync(0xffffffffu, a, o);
            if (!lane) g_scores[p] = a;
        }
        gridbar(tgt); tgt += NB;

        // ======== P2: softmax + ctx -> x fragments (blocks 0..127) ========
        if (gateblk) {
            float* red  = p2s;
            float* swp  = p2s + 256;
            float* part = p2s + 512;
            int b = bid >> 2, jblk = bid & 3;
            float v = -1e30f;
            if (tid < 256) {
                v = (tid < SS) ? __ldcg(&g_scores[b * SS + tid]) : -1e30f;
                red[tid] = v;
            }
            __syncthreads();
            for (int o = 128; o; o >>= 1) { if (tid < o) red[tid] = fmaxf(red[tid], red[tid+o]); __syncthreads(); }
            float mx = red[0]; __syncthreads();
            float e = 0.f;
            if (tid < 256) { e = (tid < SS) ? expf(v - mx) : 0.f; red[tid] = e; }
            __syncthreads();
            for (int o = 128; o; o >>= 1) { if (tid < o) red[tid] += red[tid+o]; __syncthreads(); }
            float inv = 1.f / red[0];
            if (tid < 256) swp[tid] = e * inv;
            __syncthreads();

            int jj = tid & 255, sp = tid >> 8;
            int j = jblk * 256 + jj;
            const float* mp = memory + ((size_t)b * SS + sp * 49) * HH + j;
            float acc2 = 0.f;
            #pragma unroll 7
            for (int s = 0; s < 49; s++)
                acc2 += swp[sp * 49 + s] * mp[(size_t)s * HH];
            part[sp * 256 + jj] = acc2;
            __syncthreads();
            if (tid < 256) {
                float cv = part[jj] + part[256+jj] + part[512+jj] + part[768+jj];
                g_xf[xf_off(j, b, 0)] = f2tf32(cv);
            }
            __syncthreads();
            // release: this block's ctx fragments are published
            if (tid == 0) {
                unsigned one = 1u;
                asm volatile("red.release.gpu.global.add.u32 [%0], %1;"
                             :: "l"(&g_p2done), "r"(one) : "memory");
            }
        }
        // (no grid barrier here — ctx-chunk issues are gated by g_p2done)

        // ======== P3: gates pipeline (h-half first) + cell ========
        if (gateblk) {
            if (tid < 256) {
                const int w8 = tid >> 5;
                const int mt = w8 & 1, nt = w8 >> 1;
                const int grp = lane >> 2, tg = lane & 3;
                float acc[4] = {0.f, 0.f, 0.f, 0.f};

                #pragma unroll
                for (int i = 0; i < 16; i++) {
                    uint32_t mb = (i & 1) ? mb1 : mb0;
                    MB_WAIT(mb, (i >> 1) & 1);
                    const float4* wb = (const float4*)(smem + OFF_W + (i & 1) * 16384);
                    const float2* xb = (const float2*)(smem + OFF_X + (i & 1) * 16384);
                    #pragma unroll
                    for (int c8 = 0; c8 < 16; c8++) {
                        float4 a4 = wb[(c8 * 2 + mt) * 32 + lane];
                        float2 b2 = xb[(c8 * 4 + nt) * 32 + lane];
                        mma_op(acc, (const uint32_t*)&a4, (const uint32_t*)&b2);
                    }
                    asm volatile("bar.sync 7, 256;" ::: "memory");
                    if (tid == 0 && i < 14) {
                        int nxt = (i + 2 + 8) & 15;        // h-first order
                        if (i == 6) {                      // first ctx-chunk issue: wait for all P2
                            unsigned x, want = 128u * (unsigned)(t + 1);
                            do {
                                asm volatile("ld.acquire.gpu.global.u32 %0, [%1];"
                                             : "=r"(x) : "l"(&g_p2done));
                            } while (x < want);
                        }
                        issue(nxt, i + 2);
                    }
                }

                *(float2*)&gate_s[(mt*16 + grp    ) * 32 + nt*8 + tg*2] = make_float2(acc[0], acc[1]);
                *(float2*)&gate_s[(mt*16 + grp + 8) * 32 + nt*8 + tg*2] = make_float2(acc[2], acc[3]);
            }
            __syncthreads();
            if (tid < 256) {
                int b = tid & 31, jo = tid >> 5;
                int j = bid * 8 + jo;
                float pre[4];
                #pragma unroll
                for (int g = 0; g < 4; g++) {
                    pre[g] = gate_s[(g*8 + jo) * 32 + b]
                           + __ldg(&g_ET[((size_t)t * RR + g*1024 + j) * 32 + b])
                           + __ldg(&b_ih[g*1024 + j]) + __ldg(&b_hh[g*1024 + j]);
                }
                float ig = 1.f / (1.f + expf(-pre[0]));
                float fg = 1.f / (1.f + expf(-pre[1]));
                float gg = tanhf(pre[2]);
                float og = 1.f / (1.f + expf(-pre[3]));
                int idx = b * HH + j;
                float cn = fg * g_c[idx] + ig * gg;
                float hn = og * tanhf(cn);
                g_c[idx] = cn;
                g_h[idx] = hn;
                g_xf[xf_off(1024 + j, b, (t + 1) & 1)] = f2tf32(hn);
                int m = t * 32 + b;
                int mblk = m >> 7, mtile = (m >> 4) & 7;
                int q = ((m >> 3) & 1) + 2 * ((j >> 2) & 1);
                int lnA = ((m & 7) << 2) | (j & 3);
                g_Af[((((size_t)mblk * 128 + (j >> 3)) * 8 + mtile) * 32 + lnA) * 4 + q]
                    = f2tf32(hn);
            }
        }
        gridbar(tgt); tgt += NB;
    }
}

// ---------------- pipelined logits GEMM (unchanged from R9) ----------------
__global__ __launch_bounds__(256, 2) void k_logits(
    const float* __restrict__ bias, float* __restrict__ out)
{
    extern __shared__ char smem[];
    const uint32_t sbase = smem_u32(smem);
    const int tid = threadIdx.x;
    const int mblk = blockIdx.x, nblk = blockIdx.y;
    const int warp = tid >> 5, lane = tid & 31;
    const int wm = warp >> 1, wn = warp & 1;
    const int grp = lane >> 2, tg = lane & 3;

    if (tid == 0) {
        #pragma unroll
        for (int i = 0; i < 3; i++)
            asm volatile("mbarrier.init.shared.b64 [%0], %1;"
                         :: "r"(sbase + i * 8), "r"(1u) : "memory");
    }
    __syncthreads();

    float acc[2][8][4] = {};

    auto issue = [&](int s) {
        int buf = s % 3;
        uint32_t mb = sbase + buf * 8;
        uint32_t ad = sbase + 128 + buf * 32768;
        uint32_t bd = ad + 16384;
        const float* as = g_Af + ((size_t)mblk * 128 + s * 4) * 1024;
        const float* bs = g_Wo + ((size_t)nblk * 128 + s * 4) * 1024;
        asm volatile("mbarrier.arrive.expect_tx.shared.b64 _, [%0], %1;"
                     :: "r"(mb), "r"(32768u) : "memory");
        asm volatile("cp.async.bulk.shared::cta.global.mbarrier::complete_tx::bytes "
                     "[%0], [%1], %2, [%3];"
                     :: "r"(ad), "l"(as), "r"(16384u), "r"(mb) : "memory");
        asm volatile("cp.async.bulk.shared::cta.global.mbarrier::complete_tx::bytes "
                     "[%0], [%1], %2, [%3];"
                     :: "r"(bd), "l"(bs), "r"(16384u), "r"(mb) : "memory");
    };

    if (tid == 0) { issue(0); issue(1); }

    for (int s = 0; s < 32; s++) {
        int buf = s % 3;
        MB_WAIT(sbase + buf * 8, (s / 3) & 1);
        const float4* Ab = (const float4*)(smem + 128 + buf * 32768);
        const float2* Bb = (const float2*)(smem + 128 + buf * 32768 + 16384);
        #pragma unroll
        for (int c8 = 0; c8 < 4; c8++) {
            float4 a0 = Ab[(c8 * 8 + wm * 2 + 0) * 32 + lane];
            float4 a1 = Ab[(c8 * 8 + wm * 2 + 1) * 32 + lane];
            #pragma unroll
            for (int nt = 0; nt < 8; nt++) {
                float2 b2 = Bb[(c8 * 16 + wn * 8 + nt) * 32 + lane];
                mma_op(acc[0][nt], (const uint32_t*)&a0, (const uint32_t*)&b2);
                mma_op(acc[1][nt], (const uint32_t*)&a1, (const uint32_t*)&b2);
            }
        }
        __syncthreads();
        if (tid == 0 && s + 2 < 32) issue(s + 2);
    }

    #pragma unroll
    for (int mt = 0; mt < 2; mt++) {
        int m0 = mblk * 128 + (wm * 2 + mt) * 16 + grp;
        #pragma unroll
        for (int nt = 0; nt < 8; nt++) {
            int ng = nblk * 128 + wn * 64 + nt * 8 + tg * 2;
            float b0 = __ldg(bias + ng), b1 = __ldg(bias + ng + 1);
            int m2 = m0 + 8;
            size_t r1 = ((size_t)(m0 & 31) * TT + (m0 >> 5)) * VV;
            size_t r2 = ((size_t)(m2 & 31) * TT + (m2 >> 5)) * VV;
            *(float2*)(out + r1 + ng) = make_float2(acc[mt][nt][0] + b0, acc[mt][nt][1] + b1);
            *(float2*)(out + r2 + ng) = make_float2(acc[mt][nt][2] + b0, acc[mt][nt][3] + b1);
        }
    }
}

// ---------------- small kernels ----------------
__global__ void k_zero() {
    int i = blockIdx.x * 1024 + threadIdx.x;
    g_h[i] = 0.f; g_c[i] = 0.f;
    g_xf[i] = 0.f; g_xf[i + 32768] = 0.f; g_xf[i + 65536] = 0.f;
    if (i == 0) { g_bar = 0u; g_p2done = 0u; }
}

__global__ void k_copy_hc(float* __restrict__ out) {
    int i = blockIdx.x * 512 + threadIdx.x;
    const size_t OFF = (size_t)BB * TT * VV;
    out[OFF + i] = g_h[i];
    out[OFF + (size_t)BB*HH + i] = g_c[i];
}

// ---------------- launch ----------------
extern "C" void kernel_launch(void* const* d_in, const int* in_sizes, int n_in,
                              void* d_out, int out_size)
{
    const float* memory  = (const float*)d_in[0];
    const int*   captions= (const int*  )d_in[1];
    const float* emb     = (const float*)d_in[2];
    const float* attn_W  = (const float*)d_in[3];
    const float* W_ih    = (const float*)d_in[4];
    const float* W_hh    = (const float*)d_in[5];
    const float* b_ih    = (const float*)d_in[6];
    const float* b_hh    = (const float*)d_in[7];
    const float* W_out   = (const float*)d_in[8];
    const float* b_out   = (const float*)d_in[9];
    float* out = (float*)d_out;

    static float *pM2 = nullptr, *pET = nullptr;
    if (!pM2) {
        cudaGetSymbolAddress((void**)&pM2, g_M2);
        cudaGetSymbolAddress((void**)&pET, g_ET);
        cudaFuncSetAttribute(k_recur,  cudaFuncAttributeMaxDynamicSharedMemorySize, SMEM_RECUR);
        cudaFuncSetAttribute(k_logits, cudaFuncAttributeMaxDynamicSharedMemorySize, SMEM_LOG);
    }

    k_zero<<<32, 1024>>>();

    // M2 = memory @ attn_W
    mma_gemm<<<dim3(HH/128, (BB*SS)/128), 256>>>(
        memory, attn_W, pM2, BB*SS, HH, HH, HH,
        nullptr, nullptr, 2);

    // E^T
    mma_gemm<<<dim3(RR/128, (BB*TT)/128), 256>>>(
        nullptr, W_ih, pET, BB*TT, RR, HH, 2048,
        captions, emb, 3);

    // fragment packs
    k_packWF<<<8192, 256>>>(W_ih, W_hh);
    k_packWo<<<64000, 256>>>(W_out);

    // recurrence (2 grid barriers / step)
    k_recur<<<NB, 1024, SMEM_RECUR>>>(memory, b_ih, b_hh);

    // logits
    k_logits<<<dim3(16, 250), 256, SMEM_LOG>>>(b_out, out);

    k_copy_hc<<<64, 512>>>(out);
}

// round 12
// speedup vs baseline: 1.5385x; 1.0610x over previous
#include <cuda_runtime.h>
#include <cstdint>
#include <math.h>

#define BB 32
#define SS 196
#define TT 64
#define HH 1024
#define VV 32000
#define RR 4096
#define NB 148

// k_recur smem byte offsets
#define OFF_W    128
#define OFF_X    (128 + 32768)
#define OFF_GATE (128 + 65536)
#define OFF_P2S  (OFF_GATE + 4096)
#define SMEM_RECUR (OFF_P2S + 6144)

// k_pgemm smem: 3 stages x (16KB A + 16KB B), mbarriers at base
#define SMEM_LOG (128 + 3*32768)

// ---------------- scratch ----------------
__device__ float g_M2 [(size_t)BB*SS*HH];
__device__ float g_ET [(size_t)TT*RR*BB];
__device__ float g_Wf [(size_t)128*16*4096];
__device__ float g_xf [(size_t)24*4096];
__device__ float g_Af [(size_t)16*131072];     // logits A fragments (written by recur)
__device__ float g_Wo [(size_t)32000*1024];    // logits B fragments
__device__ float g_AM2[(size_t)49*131072];     // M2 A fragments (memory)
__device__ float g_BM2[(size_t)8*131072];      // M2 B fragments (attn_W, trans)
__device__ float g_AE [(size_t)16*131072];     // E  A fragments (emb gather)
__device__ float g_BE [(size_t)32*131072];     // E  B fragments (W_ih emb half)
__device__ float g_h [BB*HH];
__device__ float g_c [BB*HH];
__device__ float g_scores[BB*SS];
__device__ unsigned g_bar;
__device__ unsigned g_p2done;

// ---------------- helpers ----------------
__device__ __forceinline__ float f2tf32(float x) {
    uint32_t u; asm("cvt.rna.tf32.f32 %0, %1;" : "=r"(u) : "f"(x));
    return __uint_as_float(u);
}
__device__ __forceinline__ void mma_op(float* c, const uint32_t* a, const uint32_t* b) {
    asm volatile(
        "mma.sync.aligned.m16n8k8.row.col.f32.tf32.tf32.f32 "
        "{%0,%1,%2,%3},{%4,%5,%6,%7},{%8,%9},{%0,%1,%2,%3};"
        : "+f"(c[0]), "+f"(c[1]), "+f"(c[2]), "+f"(c[3])
        : "r"(a[0]), "r"(a[1]), "r"(a[2]), "r"(a[3]), "r"(b[0]), "r"(b[1]));
}
__device__ __forceinline__ uint32_t smem_u32(const void* p) {
    uint32_t a;
    asm("{ .reg .u64 t; cvta.to.shared.u64 t, %1; cvt.u32.u64 %0, t; }" : "=r"(a) : "l"(p));
    return a;
}
__device__ __forceinline__ size_t xf_off(int k, int n, int parity) {
    int cc = k >> 7;
    int ccp = (cc < 8) ? cc : (cc + parity * 8);
    int c8 = (k >> 3) & 15;
    int nt = n >> 3;
    int ln = ((n & 7) << 2) | (k & 3);
    int q  = (k >> 2) & 1;
    return ((size_t)(ccp * 16 + c8) * 4 + nt) * 64 + (size_t)ln * 2 + q;
}

#define MB_WAIT(mbar, par) do { uint32_t _d; \
    do { asm volatile("{\n\t.reg .pred p;\n\t" \
        "mbarrier.try_wait.parity.acquire.cta.shared::cta.b64 p, [%1], %2;\n\t" \
        "selp.b32 %0, 1, 0, p;\n\t}" \
        : "=r"(_d) : "r"(mbar), "r"((uint32_t)(par)) : "memory"); } while (!_d); } while (0)

// ---------------- A-fragment pack (formula proven by recur's g_Af store) ----------------
// dst float4 idx: [mblk][c8:128][mtile:8][lane:32]; values:
// (m0,k0),(m0+8,k0),(m0,k0+4),(m0+8,k0+4) with m0=mblk*128+mtile*16+(lane>>2), k0=c8*8+(lane&3)
__global__ __launch_bounds__(256) void k_packA(
    const float* __restrict__ src, const int* __restrict__ gidx,
    const float* __restrict__ gtab, float* __restrict__ dst)
{
    int idx = blockIdx.x * 256 + threadIdx.x;
    int lane = idx & 31, mtile = (idx >> 5) & 7, c8 = (idx >> 8) & 127, mblk = idx >> 15;
    int m0 = mblk * 128 + mtile * 16 + (lane >> 2);
    int k0 = c8 * 8 + (lane & 3);
    const float* r0 = gidx ? (gtab + (size_t)gidx[m0    ] * HH) : (src + (size_t)m0       * HH);
    const float* r1 = gidx ? (gtab + (size_t)gidx[m0 + 8] * HH) : (src + (size_t)(m0 + 8) * HH);
    float4 v;
    v.x = f2tf32(r0[k0]);     v.y = f2tf32(r1[k0]);
    v.z = f2tf32(r0[k0 + 4]); v.w = f2tf32(r1[k0 + 4]);
    ((float4*)dst)[idx] = v;
}

// ---------------- B-fragment pack (formula = old k_packWo, parametrized) ----------------
__global__ __launch_bounds__(256) void k_packB(
    const float* __restrict__ src, float* __restrict__ dst, int ldb, int trans)
{
    size_t idx = (size_t)blockIdx.x * 256 + threadIdx.x;   // float2 id
    int lane = (int)(idx & 31);
    int nt   = (int)((idx >> 5) & 15);
    int c8   = (int)((idx >> 9) & 127);
    int nblk = (int)(idx >> 16);
    int n = nblk * 128 + nt * 8 + (lane >> 2);
    int k = c8 * 8 + (lane & 3);
    float2 v;
    if (trans) {
        v.x = f2tf32(src[(size_t)k * ldb + n]);
        v.y = f2tf32(src[(size_t)(k + 4) * ldb + n]);
    } else {
        v.x = f2tf32(src[(size_t)n * ldb + k]);
        v.y = f2tf32(src[(size_t)n * ldb + k + 4]);
    }
    ((float2*)dst)[idx] = v;
}

// ---------------- gate weight fragment pack (unchanged) ----------------
__global__ __launch_bounds__(256) void k_packWF(
    const float* __restrict__ W_ih, const float* __restrict__ W_hh)
{
    int idx = blockIdx.x * 256 + threadIdx.x;
    int lane = idx & 31;
    int mt   = (idx >> 5) & 1;
    int c8   = (idx >> 6) & 15;
    int cc   = (idx >> 10) & 15;
    int blk  = idx >> 14;
    float4 v;
    float* o = (float*)&v;
    #pragma unroll
    for (int q = 0; q < 4; q++) {
        int m = mt * 16 + (lane >> 2) + 8 * (q & 1);
        int g = m >> 3, jo = m & 7;
        int r = g * 1024 + blk * 8 + jo;
        int k = (cc * 16 + c8) * 8 + (lane & 3) + 4 * (q >> 1);
        float wv = (k < 1024) ? W_ih[(size_t)r * 2048 + 1024 + k]
                              : W_hh[(size_t)r * 1024 + (k - 1024)];
        o[q] = f2tf32(wv);
    }
    ((float4*)g_Wf)[idx] = v;
}

// ---------------- no-CCTL global barrier ----------------
__device__ __forceinline__ void gridbar(unsigned target) {
    __syncthreads();
    if (threadIdx.x == 0) {
        unsigned one = 1u, x;
        asm volatile("red.release.gpu.global.add.u32 [%0], %1;"
                     :: "l"(&g_bar), "r"(one) : "memory");
        do {
            asm volatile("ld.acquire.gpu.global.u32 %0, [%1];"
                         : "=r"(x) : "l"(&g_bar));
        } while (x < target);
    }
    __syncthreads();
}

// ---------------- persistent recurrence (unchanged from R11) ----------------
__global__ __launch_bounds__(1024, 1) void k_recur(
    const float* __restrict__ memory,
    const float* __restrict__ b_ih, const float* __restrict__ b_hh)
{
    extern __shared__ char smem[];
    float* gate_s = (float*)(smem + OFF_GATE);
    float* p2s    = (float*)(smem + OFF_P2S);
    const uint32_t sbase = smem_u32(smem);
    const uint32_t mb0 = sbase, mb1 = sbase + 8;

    const int tid = threadIdx.x, bid = blockIdx.x;
    const int w = tid >> 5, lane = tid & 31;
    const bool gateblk = (bid < 128);

    if (tid == 0) {
        asm volatile("mbarrier.init.shared.b64 [%0], %1;" :: "r"(mb0), "r"(1u) : "memory");
        asm volatile("mbarrier.init.shared.b64 [%0], %1;" :: "r"(mb1), "r"(1u) : "memory");
    }
    __syncthreads();

    unsigned tgt = NB;

    for (int t = 0; t < TT; t++) {
        const int par = t & 1;

        auto issue = [&](int cc, int slot) {
            uint32_t mb = (slot & 1) ? mb1 : mb0;
            uint32_t wd = sbase + OFF_W + (slot & 1) * 16384;
            uint32_t xd = sbase + OFF_X + (slot & 1) * 16384;
            const float* ws = g_Wf + ((size_t)bid * 16 + cc) * 4096;
            int ccp = (cc < 8) ? cc : (cc + par * 8);
            const float* xs = g_xf + (size_t)ccp * 4096;
            asm volatile("mbarrier.arrive.expect_tx.shared.b64 _, [%0], %1;"
                         :: "r"(mb), "r"(32768u) : "memory");
            asm volatile("cp.async.bulk.shared::cta.global.mbarrier::complete_tx::bytes "
                         "[%0], [%1], %2, [%3];"
                         :: "r"(wd), "l"(ws), "r"(16384u), "r"(mb) : "memory");
            asm volatile("cp.async.bulk.shared::cta.global.mbarrier::complete_tx::bytes "
                         "[%0], [%1], %2, [%3];"
                         :: "r"(xd), "l"(xs), "r"(16384u), "r"(mb) : "memory");
        };

        if (gateblk && tid == 0) { issue(8, 0); issue(9, 1); }

        // ======== P1: scores ========
        for (int p = bid * 32 + w; p < BB * SS; p += NB * 32) {
            int b = p / SS;
            const float4* m4 = (const float4*)(g_M2 + (size_t)p * HH);
            const float4* h4 = (const float4*)(g_h + b * HH);
            float a = 0.f;
            #pragma unroll
            for (int i = 0; i < 8; i++) {
                float4 mv = m4[i * 32 + lane];
                float4 hv = __ldcg(&h4[i * 32 + lane]);
                a += mv.x*hv.x + mv.y*hv.y + mv.z*hv.z + mv.w*hv.w;
            }
            #pragma unroll
            for (int o = 16; o; o >>= 1) a += __shfl_xor_sync(0xffffffffu, a, o);
            if (!lane) g_scores[p] = a;
        }
        gridbar(tgt); tgt += NB;

        // ======== P2: softmax + ctx -> x fragments ========
        if (gateblk) {
            float* red  = p2s;
            float* swp  = p2s + 256;
            float* part = p2s + 512;
            int b = bid >> 2, jblk = bid & 3;
            float v = -1e30f;
            if (tid < 256) {
                v = (tid < SS) ? __ldcg(&g_scores[b * SS + tid]) : -1e30f;
                red[tid] = v;
            }
            __syncthreads();
            for (int o = 128; o; o >>= 1) { if (tid < o) red[tid] = fmaxf(red[tid], red[tid+o]); __syncthreads(); }
            float mx = red[0]; __syncthreads();
            float e = 0.f;
            if (tid < 256) { e = (tid < SS) ? expf(v - mx) : 0.f; red[tid] = e; }
            __syncthreads();
            for (int o = 128; o; o >>= 1) { if (tid < o) red[tid] += red[tid+o]; __syncthreads(); }
            float inv = 1.f / red[0];
            if (tid < 256) swp[tid] = e * inv;
            __syncthreads();

            int jj = tid & 255, sp = tid >> 8;
            int j = jblk * 256 + jj;
            const float* mp = memory + ((size_t)b * SS + sp * 49) * HH + j;
            float acc2 = 0.f;
            #pragma unroll 7
            for (int s = 0; s < 49; s++)
                acc2 += swp[sp * 49 + s] * mp[(size_t)s * HH];
            part[sp * 256 + jj] = acc2;
            __syncthreads();
            if (tid < 256) {
                float cv = part[jj] + part[256+jj] + part[512+jj] + part[768+jj];
                g_xf[xf_off(j, b, 0)] = f2tf32(cv);
            }
            __syncthreads();
            if (tid == 0) {
                unsigned one = 1u;
                asm volatile("red.release.gpu.global.add.u32 [%0], %1;"
                             :: "l"(&g_p2done), "r"(one) : "memory");
            }
        }

        // ======== P3: gates pipeline (h-first) + cell ========
        if (gateblk) {
            if (tid < 256) {
                const int w8 = tid >> 5;
                const int mt = w8 & 1, nt = w8 >> 1;
                const int grp = lane >> 2, tg = lane & 3;
                float acc[4] = {0.f, 0.f, 0.f, 0.f};

                #pragma unroll
                for (int i = 0; i < 16; i++) {
                    uint32_t mb = (i & 1) ? mb1 : mb0;
                    MB_WAIT(mb, (i >> 1) & 1);
                    const float4* wb = (const float4*)(smem + OFF_W + (i & 1) * 16384);
                    const float2* xb = (const float2*)(smem + OFF_X + (i & 1) * 16384);
                    #pragma unroll
                    for (int c8 = 0; c8 < 16; c8++) {
                        float4 a4 = wb[(c8 * 2 + mt) * 32 + lane];
                        float2 b2 = xb[(c8 * 4 + nt) * 32 + lane];
                        mma_op(acc, (const uint32_t*)&a4, (const uint32_t*)&b2);
                    }
                    asm volatile("bar.sync 7, 256;" ::: "memory");
                    if (tid == 0 && i < 14) {
                        int nxt = (i + 2 + 8) & 15;
                        if (i == 6) {
                            unsigned x, want = 128u * (unsigned)(t + 1);
                            do {
                                asm volatile("ld.acquire.gpu.global.u32 %0, [%1];"
                                             : "=r"(x) : "l"(&g_p2done));
                            } while (x < want);
                        }
                        issue(nxt, i + 2);
                    }
                }

                *(float2*)&gate_s[(mt*16 + grp    ) * 32 + nt*8 + tg*2] = make_float2(acc[0], acc[1]);
                *(float2*)&gate_s[(mt*16 + grp + 8) * 32 + nt*8 + tg*2] = make_float2(acc[2], acc[3]);
            }
            __syncthreads();
            if (tid < 256) {
                int b = tid & 31, jo = tid >> 5;
                int j = bid * 8 + jo;
                float pre[4];
                #pragma unroll
                for (int g = 0; g < 4; g++) {
                    pre[g] = gate_s[(g*8 + jo) * 32 + b]
                           + __ldg(&g_ET[((size_t)t * RR + g*1024 + j) * 32 + b])
                           + __ldg(&b_ih[g*1024 + j]) + __ldg(&b_hh[g*1024 + j]);
                }
                float ig = 1.f / (1.f + expf(-pre[0]));
                float fg = 1.f / (1.f + expf(-pre[1]));
                float gg = tanhf(pre[2]);
                float og = 1.f / (1.f + expf(-pre[3]));
                int idx = b * HH + j;
                float cn = fg * g_c[idx] + ig * gg;
                float hn = og * tanhf(cn);
                g_c[idx] = cn;
                g_h[idx] = hn;
                g_xf[xf_off(1024 + j, b, (t + 1) & 1)] = f2tf32(hn);
                int m = t * 32 + b;
                int mblk = m >> 7, mtile = (m >> 4) & 7;
                int q = ((m >> 3) & 1) + 2 * ((j >> 2) & 1);
                int lnA = ((m & 7) << 2) | (j & 3);
                g_Af[((((size_t)mblk * 128 + (j >> 3)) * 8 + mtile) * 32 + lnA) * 4 + q]
                    = f2tf32(hn);
            }
        }
        gridbar(tgt); tgt += NB;
    }
}

// ---------------- generalized pipelined GEMM (from proven k_logits) ----------------
// A: Afrag [mblk][c8][mtile][lane][4] ; B: Bfrag [nblk][c8][ntile][lane][2] ; K=1024
// mode 0: C[m*Nn + n]                (row-major)
// mode 1: logits: m=t*32+b -> C[(b*T+t)*Nn + n] + bias[n]
// mode 2: E-transpose: m=b*64+t -> C[(t*RR + n)*32 + b]
__global__ __launch_bounds__(256, 2) void k_pgemm(
    const float* __restrict__ Afrag, const float* __restrict__ Bfrag,
    float* __restrict__ C, int Nn, int mode, const float* __restrict__ bias)
{
    extern __shared__ char smem[];
    const uint32_t sbase = smem_u32(smem);
    const int tid = threadIdx.x;
    const int mblk = blockIdx.x, nblk = blockIdx.y;
    const int warp = tid >> 5, lane = tid & 31;
    const int wm = warp >> 1, wn = warp & 1;
    const int grp = lane >> 2, tg = lane & 3;

    if (tid == 0) {
        #pragma unroll
        for (int i = 0; i < 3; i++)
            asm volatile("mbarrier.init.shared.b64 [%0], %1;"
                         :: "r"(sbase + i * 8), "r"(1u) : "memory");
    }
    __syncthreads();

    float acc[2][8][4] = {};

    auto issue = [&](int s) {
        int buf = s % 3;
        uint32_t mb = sbase + buf * 8;
        uint32_t ad = sbase + 128 + buf * 32768;
        uint32_t bd = ad + 16384;
        const float* as = Afrag + ((size_t)mblk * 128 + s * 4) * 1024;
        const float* bs = Bfrag + ((size_t)nblk * 128 + s * 4) * 1024;
        asm volatile("mbarrier.arrive.expect_tx.shared.b64 _, [%0], %1;"
                     :: "r"(mb), "r"(32768u) : "memory");
        asm volatile("cp.async.bulk.shared::cta.global.mbarrier::complete_tx::bytes "
                     "[%0], [%1], %2, [%3];"
                     :: "r"(ad), "l"(as), "r"(16384u), "r"(mb) : "memory");
        asm volatile("cp.async.bulk.shared::cta.global.mbarrier::complete_tx::bytes "
                     "[%0], [%1], %2, [%3];"
                     :: "r"(bd), "l"(bs), "r"(16384u), "r"(mb) : "memory");
    };

    if (tid == 0) { issue(0); issue(1); }

    for (int s = 0; s < 32; s++) {
        int buf = s % 3;
        MB_WAIT(sbase + buf * 8, (s / 3) & 1);
        const float4* Ab = (const float4*)(smem + 128 + buf * 32768);
        const float2* Bb = (const float2*)(smem + 128 + buf * 32768 + 16384);
        #pragma unroll
        for (int c8 = 0; c8 < 4; c8++) {
            float4 a0 = Ab[(c8 * 8 + wm * 2 + 0) * 32 + lane];
            float4 a1 = Ab[(c8 * 8 + wm * 2 + 1) * 32 + lane];
            #pragma unroll
            for (int nt = 0; nt < 8; nt++) {
                float2 b2 = Bb[(c8 * 16 + wn * 8 + nt) * 32 + lane];
                mma_op(acc[0][nt], (const uint32_t*)&a0, (const uint32_t*)&b2);
                mma_op(acc[1][nt], (const uint32_t*)&a1, (const uint32_t*)&b2);
            }
        }
        __syncthreads();
        if (tid == 0 && s + 2 < 32) issue(s + 2);
    }

    #pragma unroll
    for (int mt = 0; mt < 2; mt++) {
        int m0 = mblk * 128 + (wm * 2 + mt) * 16 + grp;
        int m2 = m0 + 8;
        #pragma unroll
        for (int nt = 0; nt < 8; nt++) {
            int ng = nblk * 128 + wn * 64 + nt * 8 + tg * 2;
            float* a4 = acc[mt][nt];
            if (mode == 1) {
                float b0 = __ldg(bias + ng), b1 = __ldg(bias + ng + 1);
                size_t r1 = ((size_t)(m0 & 31) * TT + (m0 >> 5)) * Nn;
                size_t r2 = ((size_t)(m2 & 31) * TT + (m2 >> 5)) * Nn;
                *(float2*)(C + r1 + ng) = make_float2(a4[0] + b0, a4[1] + b1);
                *(float2*)(C + r2 + ng) = make_float2(a4[2] + b0, a4[3] + b1);
            } else if (mode == 2) {
                int b1i = m0 >> 6, t1 = m0 & 63;
                int b2i = m2 >> 6, t2 = m2 & 63;
                size_t p1 = ((size_t)t1 * RR + ng) * 32 + b1i;
                size_t p2 = ((size_t)t2 * RR + ng) * 32 + b2i;
                C[p1] = a4[0]; C[p1 + 32] = a4[1];
                C[p2] = a4[2]; C[p2 + 32] = a4[3];
            } else {
                *(float2*)(C + (size_t)m0 * Nn + ng) = make_float2(a4[0], a4[1]);
                *(float2*)(C + (size_t)m2 * Nn + ng) = make_float2(a4[2], a4[3]);
            }
        }
    }
}

// ---------------- small kernels ----------------
__global__ void k_zero() {
    int i = blockIdx.x * 1024 + threadIdx.x;
    g_h[i] = 0.f; g_c[i] = 0.f;
    g_xf[i] = 0.f; g_xf[i + 32768] = 0.f; g_xf[i + 65536] = 0.f;
    if (i == 0) { g_bar = 0u; g_p2done = 0u; }
}

__global__ void k_copy_hc(float* __restrict__ out) {
    int i = blockIdx.x * 512 + threadIdx.x;
    const size_t OFF = (size_t)BB * TT * VV;
    out[OFF + i] = g_h[i];
    out[OFF + (size_t)BB*HH + i] = g_c[i];
}

// ---------------- launch ----------------
extern "C" void kernel_launch(void* const* d_in, const int* in_sizes, int n_in,
                              void* d_out, int out_size)
{
    const float* memory  = (const float*)d_in[0];
    const int*   captions= (const int*  )d_in[1];
    const float* emb     = (const float*)d_in[2];
    const float* attn_W  = (const float*)d_in[3];
    const float* W_ih    = (const float*)d_in[4];
    const float* W_hh    = (const float*)d_in[5];
    const float* b_ih    = (const float*)d_in[6];
    const float* b_hh    = (const float*)d_in[7];
    const float* W_out   = (const float*)d_in[8];
    const float* b_out   = (const float*)d_in[9];
    float* out = (float*)d_out;

    static float *pM2 = nullptr, *pET = nullptr, *pAf = nullptr, *pWo = nullptr,
                 *pAM2 = nullptr, *pBM2 = nullptr, *pAE = nullptr, *pBE = nullptr;
    if (!pM2) {
        cudaGetSymbolAddress((void**)&pM2,  g_M2);
        cudaGetSymbolAddress((void**)&pET,  g_ET);
        cudaGetSymbolAddress((void**)&pAf,  g_Af);
        cudaGetSymbolAddress((void**)&pWo,  g_Wo);
        cudaGetSymbolAddress((void**)&pAM2, g_AM2);
        cudaGetSymbolAddress((void**)&pBM2, g_BM2);
        cudaGetSymbolAddress((void**)&pAE,  g_AE);
        cudaGetSymbolAddress((void**)&pBE,  g_BE);
        cudaFuncSetAttribute(k_recur, cudaFuncAttributeMaxDynamicSharedMemorySize, SMEM_RECUR);
        cudaFuncSetAttribute(k_pgemm, cudaFuncAttributeMaxDynamicSharedMemorySize, SMEM_LOG);
    }

    k_zero<<<32, 1024>>>();

    // fragment packs
    k_packA<<<6272, 256>>>(memory, nullptr, nullptr, pAM2);          // M2 A (49 mblks)
    k_packB<<<2048, 256>>>(attn_W, pBM2, HH, 1);                     // M2 B (8 nblks, trans)
    k_packA<<<2048, 256>>>(nullptr, captions, emb, pAE);             // E A (16 mblks, gather)
    k_packB<<<8192, 256>>>(W_ih, pBE, 2048, 0);                      // E B (32 nblks)
    k_packWF<<<8192, 256>>>(W_ih, W_hh);                             // gate weights
    k_packB<<<64000, 256>>>(W_out, pWo, HH, 0);                      // logits B (250 nblks)

    // M2 = memory @ attn_W  (row-major epilogue)
    k_pgemm<<<dim3(49, 8), 256, SMEM_LOG>>>(pAM2, pBM2, pM2, HH, 0, nullptr);

    // E^T = (emb[captions] @ W_ih_emb^T) -> [t][r][b]
    k_pgemm<<<dim3(16, 32), 256, SMEM_LOG>>>(pAE, pBE, pET, RR, 2, nullptr);

    // recurrence
    k_recur<<<NB, 1024, SMEM_RECUR>>>(memory, b_ih, b_hh);

    // logits
    k_pgemm<<<dim3(16, 250), 256, SMEM_LOG>>>(pAf, pWo, out, VV, 1, b_out);

    k_copy_hc<<<64, 512>>>(out);
}